// round 8
// baseline (speedup 1.0000x reference)
#include <cuda_runtime.h>
#include <cuda_bf16.h>
#include <cstdint>
#include <cstddef>

#define NGN 100000
#define NDN 100000
#define NE  400000
#define NEL 200000
#define CC  128
#define TM  128
#define TILES ((NGN + TM - 1) / TM)      // 782 (even)
#define PAIRS (TILES / 2)                // 391
#define CHUNK_ELEMS 8192                 // 128 rows * 64 bf16 = 16KB
#define TILE_IMG_ELEMS (2 * CHUNK_ELEMS) // 32KB image (2 chunks)

// smem layout (bytes): per-tile A images (hi+lo), then current-stage W images
#define SM_A(tile) ((tile) * 65536)      // hi at +0, lo at +32768
#define SM_WH  131072
#define SM_WL  163840
#define SMEM_TOTAL 196608

// ---------------------------------------------------------------------------
__device__ __align__(16) __nv_bfloat16 g_wimg[4][2][TILE_IMG_ELEMS]; // [mat][hi/lo]
__device__ __align__(16) float g_ug[(size_t)NGN * CC];
__device__ __align__(16) float g_ud[(size_t)NDN * CC];
__device__ unsigned char g_mask_g[NGN];
__device__ unsigned char g_mask_d[NDN];

// ---------------------------------------------------------------------------
__device__ __forceinline__ uint32_t smem_u32(const void* p) {
    uint32_t a;
    asm("{ .reg .u64 t; cvta.to.shared.u64 t, %1; cvt.u32.u64 %0, t; }"
        : "=r"(a) : "l"(p));
    return a;
}
__device__ __forceinline__ uint32_t swz(uint32_t off) {   // SW128 swizzle
    return off ^ ((off >> 3) & 0x70);
}

#define LDSM_X4(r0, r1, r2, r3, addr) \
    asm volatile("ldmatrix.sync.aligned.m8n8.x4.shared.b16 {%0,%1,%2,%3}, [%4];" \
        : "=r"(r0), "=r"(r1), "=r"(r2), "=r"(r3) : "r"(addr))

#define MMA16816(c, a, b) \
    asm volatile("mma.sync.aligned.m16n8k16.row.col.f32.bf16.bf16.f32 " \
        "{%0,%1,%2,%3}, {%4,%5,%6,%7}, {%8,%9}, {%0,%1,%2,%3};" \
        : "+f"((c)[0]), "+f"((c)[1]), "+f"((c)[2]), "+f"((c)[3]) \
        : "r"((a)[0]), "r"((a)[1]), "r"((a)[2]), "r"((a)[3]), \
          "r"((b)[0]), "r"((b)[1]))

// split fp32 -> bf16 hi + bf16 lo (residual)
__device__ __forceinline__ void split4(const float4 v, uint2& hv, uint2& lv) {
    __nv_bfloat16 h0 = __float2bfloat16(v.x), h1 = __float2bfloat16(v.y);
    __nv_bfloat16 h2 = __float2bfloat16(v.z), h3 = __float2bfloat16(v.w);
    float l0 = v.x - __bfloat162float(h0), l1 = v.y - __bfloat162float(h1);
    float l2 = v.z - __bfloat162float(h2), l3 = v.w - __bfloat162float(h3);
    __nv_bfloat162 hp0(h0, h1), hp1(h2, h3);
    __nv_bfloat162 lp0(__float2bfloat16(l0), __float2bfloat16(l1));
    __nv_bfloat162 lp1(__float2bfloat16(l2), __float2bfloat16(l3));
    hv.x = *(uint32_t*)&hp0; hv.y = *(uint32_t*)&hp1;
    lv.x = *(uint32_t*)&lp0; lv.y = *(uint32_t*)&lp1;
}
__device__ __forceinline__ void split2(float v0, float v1, uint32_t& h, uint32_t& l) {
    __nv_bfloat16 h0 = __float2bfloat16(v0), h1 = __float2bfloat16(v1);
    float l0 = v0 - __bfloat162float(h0), l1 = v1 - __bfloat162float(h1);
    __nv_bfloat162 hp(h0, h1);
    __nv_bfloat162 lp(__float2bfloat16(l0), __float2bfloat16(l1));
    h = *(uint32_t*)&hp; l = *(uint32_t*)&lp;
}

// ---------------------------------------------------------------------------
__global__ void init_masks_kernel() {
    int i = blockIdx.x * blockDim.x + threadIdx.x;
    if (i < NGN) g_mask_g[i] = 0;
    if (i < NDN) g_mask_d[i] = 0;
}
__global__ void scatter_masks_kernel(const int* __restrict__ dst_g2d,
                                     const int* __restrict__ dst_d2g) {
    int e = blockIdx.x * blockDim.x + threadIdx.x;
    if (e < NE) {
        g_mask_d[dst_g2d[e]] = 1;
        g_mask_g[dst_d2g[e]] = 1;
    }
}

// ---------------------------------------------------------------------------
// W split: W[128,128] (K x N) -> W^T image [n][k] bf16 hi/lo, SW128-swizzled.
// block b: 0=Wn_g 1=Wn_d 2=W1[:128] 3=W1[128:]
// ---------------------------------------------------------------------------
__global__ __launch_bounds__(256) void wsplit_kernel(
    const float* __restrict__ Wg, const float* __restrict__ Wd,
    const float* __restrict__ W1)
{
    const float* W = (blockIdx.x == 0) ? Wg : (blockIdx.x == 1) ? Wd
                   : (blockIdx.x == 2) ? W1 : (W1 + CC * CC);
    int n = threadIdx.x >> 1;
    int c = threadIdx.x & 1;
    char* ph = (char*)&g_wimg[blockIdx.x][0][(size_t)c * CHUNK_ELEMS];
    char* pl = (char*)&g_wimg[blockIdx.x][1][(size_t)c * CHUNK_ELEMS];
    #pragma unroll
    for (int kk = 0; kk < 64; kk += 4) {
        int k = c * 64 + kk;
        float4 v = make_float4(W[(size_t)(k + 0) * CC + n], W[(size_t)(k + 1) * CC + n],
                               W[(size_t)(k + 2) * CC + n], W[(size_t)(k + 3) * CC + n]);
        uint2 hv, lv;
        split4(v, hv, lv);
        uint32_t off = swz((uint32_t)(n * 128 + kk * 2));
        *(uint2*)(ph + off) = hv;
        *(uint2*)(pl + off) = lv;
    }
}

// ---------------------------------------------------------------------------
// 3-pass split-bf16 MMA, warp tile 32 rows x 64 cols.
// wm in 0..3 (32-row quarters), wn in 0..1 (64-col halves).
// acc[mt 0..1][j 0..7][4]
// ---------------------------------------------------------------------------
__device__ __forceinline__ void mma_stage(
    uint32_t abh, uint32_t abl, uint32_t bbh, uint32_t bbl,
    int wm, int wn, int lane, float acc[2][8][4])
{
    const int g = lane >> 3;
    const int r7 = lane & 7;
    const int arow = ((g & 1) << 3) + r7;
    const int akseg = (g >> 1) << 4;
    const int brow = ((g >> 1) << 3) + r7;
    const int bkseg = (g & 1) << 4;

    #pragma unroll
    for (int p = 0; p < 3; ++p) {             // (Ah,Wh), (Ah,Wl), (Al,Wh)
        const uint32_t ab = (p == 2) ? abl : abh;
        const uint32_t bb = (p == 1) ? bbl : bbh;
        #pragma unroll
        for (int kt = 0; kt < 8; ++kt) {
            const uint32_t coff = (uint32_t)(kt >> 2) * 16384u;
            const int kb = (kt & 3) * 32;

            uint32_t a[2][4];
            #pragma unroll
            for (int mt = 0; mt < 2; ++mt) {
                int row = wm * 32 + mt * 16 + arow;
                uint32_t addr = ab + coff + swz((uint32_t)(row * 128 + kb + akseg));
                LDSM_X4(a[mt][0], a[mt][1], a[mt][2], a[mt][3], addr);
            }
            #pragma unroll
            for (int gb = 0; gb < 2; ++gb) {   // two 32-col groups
                uint32_t b[4][2];
                #pragma unroll
                for (int h = 0; h < 2; ++h) {
                    int n = wn * 64 + gb * 32 + h * 16 + brow;
                    uint32_t addr = bb + coff + swz((uint32_t)(n * 128 + kb + bkseg));
                    uint32_t r0, r1, r2, r3;
                    LDSM_X4(r0, r1, r2, r3, addr);
                    b[h * 2][0] = r0;     b[h * 2][1] = r1;
                    b[h * 2 + 1][0] = r2; b[h * 2 + 1][1] = r3;
                }
                #pragma unroll
                for (int mt = 0; mt < 2; ++mt)
                    #pragma unroll
                    for (int nt = 0; nt < 4; ++nt)
                        MMA16816(acc[mt][gb * 4 + nt], a[mt], b[nt]);
            }
        }
    }
}

// ---------------------------------------------------------------------------
// Fused two-tile kernel (512 threads = 2 tiles x 8 warps, 32x64 warp tiles):
//   z = relu(x@Wa + bias1) * mask ; u = z@Wb (+ bias2)
// blocks [0,PAIRS) = gene side, [PAIRS, 2*PAIRS) = disease side.
// ---------------------------------------------------------------------------
__global__ __launch_bounds__(512, 1) void fused_gemm_kernel(
    const float* __restrict__ Xg, const float* __restrict__ Xd,
    const float* __restrict__ bn_g, const float* __restrict__ bn_d,
    const float* __restrict__ b1,
    float* __restrict__ z_gen, float* __restrict__ z_dis)
{
    extern __shared__ char smem[];
    const uint32_t sb = smem_u32(smem);
    const int tid = threadIdx.x;
    const int lane = tid & 31;
    const int wid = tid >> 5;
    const int wtile = wid >> 3;          // which of the 2 tiles
    const int w8 = wid & 7;
    const int wm = w8 >> 1;              // 4 row-quarters (32 rows)
    const int wn = w8 & 1;               // 2 col-halves (64 cols)

    const bool sideB = (blockIdx.x >= PAIRS);
    const int t0 = (sideB ? (blockIdx.x - PAIRS) : blockIdx.x) * 2;
    const float* X = sideB ? Xd : Xg;
    const float* bias1 = sideB ? bn_d : bn_g;
    const float* bias2 = sideB ? b1 : nullptr;
    const unsigned char* mask = sideB ? g_mask_d : g_mask_g;
    float* zout = sideB ? z_dis : z_gen;
    float* uout = sideB ? g_ud : g_ug;
    const __nv_bfloat16* w1h = g_wimg[sideB ? 1 : 0][0];
    const __nv_bfloat16* w1l = g_wimg[sideB ? 1 : 0][1];
    const __nv_bfloat16* w2h = g_wimg[sideB ? 3 : 2][0];
    const __nv_bfloat16* w2l = g_wimg[sideB ? 3 : 2][1];
    const int M = sideB ? NDN : NGN;

    // ---- stage x (2 tiles) -> bf16 hi/lo swizzled images; copy W1 images ----
    {
        #pragma unroll
        for (int tile = 0; tile < 2; ++tile) {
            const int rows_left = M - (t0 + tile) * TM;
            const float4* xs = (const float4*)(X + (size_t)(t0 + tile) * TM * CC);
            #pragma unroll
            for (int i = 0; i < 8; ++i) {
                int q = i * 512 + tid;          // float4 index within tile
                int row = q >> 5;
                int kk = (q & 31) << 2;
                float4 v = (row < rows_left) ? xs[q] : make_float4(0.f, 0.f, 0.f, 0.f);
                uint2 hv, lv;
                split4(v, hv, lv);
                uint32_t off = (uint32_t)((kk >> 6) * 16384)
                             + swz((uint32_t)(row * 128 + (kk & 63) * 2));
                *(uint2*)(smem + SM_A(tile) + off) = hv;
                *(uint2*)(smem + SM_A(tile) + 32768 + off) = lv;
            }
        }
        const uint4* s1h = (const uint4*)w1h;
        const uint4* s1l = (const uint4*)w1l;
        uint4* dh = (uint4*)(smem + SM_WH);
        uint4* dl = (uint4*)(smem + SM_WL);
        #pragma unroll
        for (int i = 0; i < 4; ++i) {
            dh[i * 512 + tid] = s1h[i * 512 + tid];
            dl[i * 512 + tid] = s1l[i * 512 + tid];
        }
    }
    __syncthreads();

    float acc[2][8][4];
    #pragma unroll
    for (int mt = 0; mt < 2; ++mt)
        #pragma unroll
        for (int j = 0; j < 8; ++j)
            #pragma unroll
            for (int q = 0; q < 4; ++q) acc[mt][j][q] = 0.0f;

    // ---- stage 1: z = x @ Wa ----
    mma_stage(sb + SM_A(wtile), sb + SM_A(wtile) + 32768,
              sb + SM_WH, sb + SM_WL, wm, wn, lane, acc);
    __syncthreads();   // all warps done reading A and W1 images

    // ---- reload W buffers with stage-2 images (overlaps epilogue latency) ----
    {
        const uint4* s2h = (const uint4*)w2h;
        const uint4* s2l = (const uint4*)w2l;
        uint4* dh = (uint4*)(smem + SM_WH);
        uint4* dl = (uint4*)(smem + SM_WL);
        #pragma unroll
        for (int i = 0; i < 4; ++i) {
            dh[i * 512 + tid] = s2h[i * 512 + tid];
            dl[i * 512 + tid] = s2l[i * 512 + tid];
        }
    }

    // ---- epilogue 1: bias + relu*mask, write z, re-split into A buffers ----
    const int row_base = (t0 + wtile) * TM;
    #pragma unroll
    for (int mt = 0; mt < 2; ++mt) {
        const int rl0 = wm * 32 + mt * 16 + (lane >> 2);
        #pragma unroll
        for (int j = 0; j < 8; ++j) {
            const int col = wn * 64 + j * 8 + 2 * (lane & 3);
            const float2 bv = *(const float2*)&bias1[col];
            #pragma unroll
            for (int hh = 0; hh < 2; ++hh) {
                const int rl = rl0 + hh * 8;
                const int r = row_base + rl;
                float v0 = acc[mt][j][hh * 2 + 0] + bv.x;
                float v1 = acc[mt][j][hh * 2 + 1] + bv.y;
                if (r < M) {
                    const float mmv = (float)mask[r];
                    v0 = fmaxf(v0, 0.0f) * mmv;
                    v1 = fmaxf(v1, 0.0f) * mmv;
                    *(float2*)(zout + (size_t)r * CC + col) = make_float2(v0, v1);
                    uint32_t h, l;
                    split2(v0, v1, h, l);
                    uint32_t off = (uint32_t)((col >> 6) * 16384)
                                 + swz((uint32_t)(rl * 128 + (col & 63) * 2));
                    *(uint32_t*)(smem + SM_A(wtile) + off) = h;
                    *(uint32_t*)(smem + SM_A(wtile) + 32768 + off) = l;
                }
            }
        }
    }
    __syncthreads();

    // ---- stage 2: u = z @ Wb ----
    #pragma unroll
    for (int mt = 0; mt < 2; ++mt)
        #pragma unroll
        for (int j = 0; j < 8; ++j)
            #pragma unroll
            for (int q = 0; q < 4; ++q) acc[mt][j][q] = 0.0f;

    mma_stage(sb + SM_A(wtile), sb + SM_A(wtile) + 32768,
              sb + SM_WH, sb + SM_WL, wm, wn, lane, acc);

    // ---- epilogue 2: (+bias2), write u ----
    #pragma unroll
    for (int mt = 0; mt < 2; ++mt) {
        const int rl0 = wm * 32 + mt * 16 + (lane >> 2);
        #pragma unroll
        for (int j = 0; j < 8; ++j) {
            const int col = wn * 64 + j * 8 + 2 * (lane & 3);
            float2 bv = bias2 ? *(const float2*)&bias2[col] : make_float2(0.f, 0.f);
            #pragma unroll
            for (int hh = 0; hh < 2; ++hh) {
                const int r = row_base + rl0 + hh * 8;
                if (r < M) {
                    float v0 = acc[mt][j][hh * 2 + 0] + bv.x;
                    float v1 = acc[mt][j][hh * 2 + 1] + bv.y;
                    *(float2*)(uout + (size_t)r * CC + col) = make_float2(v0, v1);
                }
            }
        }
    }
}

// ---------------------------------------------------------------------------
// Link prediction head: one warp per labeled edge.
// ---------------------------------------------------------------------------
__global__ __launch_bounds__(256) void pred_kernel(
    const int* __restrict__ erow, const int* __restrict__ ecol,
    const float* __restrict__ W2, const float* __restrict__ b2,
    float* __restrict__ pred)
{
    int warp = (blockIdx.x * blockDim.x + threadIdx.x) >> 5;
    int lane = threadIdx.x & 31;
    if (warp >= NEL) return;

    int r = erow[warp];
    int c = ecol[warp];
    const float4 ug = *(const float4*)(g_ug + (size_t)r * CC + lane * 4);
    const float4 ud = *(const float4*)(g_ud + (size_t)c * CC + lane * 4);
    const float4 w2 = *(const float4*)(W2 + lane * 4);

    float s = fmaxf(ug.x + ud.x, 0.f) * w2.x
            + fmaxf(ug.y + ud.y, 0.f) * w2.y
            + fmaxf(ug.z + ud.z, 0.f) * w2.z
            + fmaxf(ug.w + ud.w, 0.f) * w2.w;

    #pragma unroll
    for (int o = 16; o > 0; o >>= 1)
        s += __shfl_xor_sync(0xFFFFFFFFu, s, o);

    if (lane == 0) pred[warp] = s + b2[0];
}

// ---------------------------------------------------------------------------
extern "C" void kernel_launch(void* const* d_in, const int* in_sizes, int n_in,
                              void* d_out, int out_size)
{
    (void)in_sizes; (void)n_in; (void)out_size;

    const float* x_gene    = (const float*)d_in[0];
    const float* x_disease = (const float*)d_in[1];
    const int*   ei_g2d    = (const int*)d_in[2];
    const int*   ei_d2g    = (const int*)d_in[3];
    const int*   eli       = (const int*)d_in[6];
    const float* Wn_g      = (const float*)d_in[7];
    const float* bn_g      = (const float*)d_in[8];
    const float* Wn_d      = (const float*)d_in[9];
    const float* bn_d      = (const float*)d_in[10];
    const float* W1        = (const float*)d_in[17];
    const float* b1        = (const float*)d_in[18];
    const float* W2        = (const float*)d_in[19];
    const float* b2        = (const float*)d_in[20];

    float* out   = (float*)d_out;
    float* pred  = out;
    float* z_gen = out + NEL;
    float* z_dis = out + NEL + (size_t)NGN * CC;

    cudaFuncSetAttribute(fused_gemm_kernel,
                         cudaFuncAttributeMaxDynamicSharedMemorySize, SMEM_TOTAL);

    // 1) isolation masks
    init_masks_kernel<<<(NGN + 255) / 256, 256>>>();
    scatter_masks_kernel<<<(NE + 255) / 256, 256>>>(ei_g2d + NE, ei_d2g + NE);

    // 2) weight split images (4 x 32KB hi + 32KB lo, swizzled W^T)
    wsplit_kernel<<<4, 256>>>(Wn_g, Wn_d, W1);

    // 3) fused (z, u) for both node types, two tiles per block
    fused_gemm_kernel<<<2 * PAIRS, 512, SMEM_TOTAL>>>(
        x_gene, x_disease, bn_g, bn_d, b1, z_gen, z_dis);

    // 4) edge scores
    pred_kernel<<<(NEL * 32 + 255) / 256, 256>>>(eli, eli + NEL, W2, b2, pred);
}

// round 9
// speedup vs baseline: 1.5128x; 1.5128x over previous
#include <cuda_runtime.h>
#include <cuda_bf16.h>
#include <cstdint>
#include <cstddef>

#define NGN 100000
#define NDN 100000
#define NE  400000
#define NEL 200000
#define CC  128
#define TM  128
#define TILES ((NGN + TM - 1) / TM)      // 782
#define CHUNK_ELEMS 8192                 // 128 rows * 64 bf16 = 16KB
#define TILE_IMG_ELEMS (2 * CHUNK_ELEMS) // 32KB image (2 chunks)

// smem layout (bytes): A-hi, A-lo (reused for Z-hi/Z-lo), W1 hi/lo, W2 hi/lo
#define SM_AH   0
#define SM_AL   32768
#define SM_W1H  65536
#define SM_W1L  98304
#define SM_W2H  131072
#define SM_W2L  163840
#define SMEM_TOTAL 196608

// ---------------------------------------------------------------------------
__device__ __align__(16) __nv_bfloat16 g_wimg[4][2][TILE_IMG_ELEMS]; // [mat][hi/lo]
__device__ __align__(16) float g_ug[(size_t)NGN * CC];
__device__ __align__(16) float g_ud[(size_t)NDN * CC];
__device__ unsigned char g_mask_g[NGN];
__device__ unsigned char g_mask_d[NDN];

// ---------------------------------------------------------------------------
__device__ __forceinline__ uint32_t smem_u32(const void* p) {
    uint32_t a;
    asm("{ .reg .u64 t; cvta.to.shared.u64 t, %1; cvt.u32.u64 %0, t; }"
        : "=r"(a) : "l"(p));
    return a;
}
__device__ __forceinline__ uint32_t swz(uint32_t off) {   // SW128 swizzle
    return off ^ ((off >> 3) & 0x70);
}

#define LDSM_X4(r0, r1, r2, r3, addr) \
    asm volatile("ldmatrix.sync.aligned.m8n8.x4.shared.b16 {%0,%1,%2,%3}, [%4];" \
        : "=r"(r0), "=r"(r1), "=r"(r2), "=r"(r3) : "r"(addr))

#define MMA16816(c, a, b) \
    asm volatile("mma.sync.aligned.m16n8k16.row.col.f32.bf16.bf16.f32 " \
        "{%0,%1,%2,%3}, {%4,%5,%6,%7}, {%8,%9}, {%0,%1,%2,%3};" \
        : "+f"((c)[0]), "+f"((c)[1]), "+f"((c)[2]), "+f"((c)[3]) \
        : "r"((a)[0]), "r"((a)[1]), "r"((a)[2]), "r"((a)[3]), \
          "r"((b)[0]), "r"((b)[1]))

// split fp32 -> bf16 hi + bf16 lo (residual)
__device__ __forceinline__ void split4(const float4 v, uint2& hv, uint2& lv) {
    __nv_bfloat16 h0 = __float2bfloat16(v.x), h1 = __float2bfloat16(v.y);
    __nv_bfloat16 h2 = __float2bfloat16(v.z), h3 = __float2bfloat16(v.w);
    float l0 = v.x - __bfloat162float(h0), l1 = v.y - __bfloat162float(h1);
    float l2 = v.z - __bfloat162float(h2), l3 = v.w - __bfloat162float(h3);
    __nv_bfloat162 hp0(h0, h1), hp1(h2, h3);
    __nv_bfloat162 lp0(__float2bfloat16(l0), __float2bfloat16(l1));
    __nv_bfloat162 lp1(__float2bfloat16(l2), __float2bfloat16(l3));
    hv.x = *(uint32_t*)&hp0; hv.y = *(uint32_t*)&hp1;
    lv.x = *(uint32_t*)&lp0; lv.y = *(uint32_t*)&lp1;
}
__device__ __forceinline__ void split2(float v0, float v1, uint32_t& h, uint32_t& l) {
    __nv_bfloat16 h0 = __float2bfloat16(v0), h1 = __float2bfloat16(v1);
    float l0 = v0 - __bfloat162float(h0), l1 = v1 - __bfloat162float(h1);
    __nv_bfloat162 hp(h0, h1);
    __nv_bfloat162 lp(__float2bfloat16(l0), __float2bfloat16(l1));
    h = *(uint32_t*)&hp; l = *(uint32_t*)&lp;
}

// ---------------------------------------------------------------------------
__global__ void init_masks_kernel() {
    int i = blockIdx.x * blockDim.x + threadIdx.x;
    if (i < NGN) g_mask_g[i] = 0;
    if (i < NDN) g_mask_d[i] = 0;
}
__global__ void scatter_masks_kernel(const int* __restrict__ dst_g2d,
                                     const int* __restrict__ dst_d2g) {
    int e = blockIdx.x * blockDim.x + threadIdx.x;
    if (e < NE) {
        g_mask_d[dst_g2d[e]] = 1;
        g_mask_g[dst_d2g[e]] = 1;
    }
}

// ---------------------------------------------------------------------------
// W split: W[128,128] (K x N) -> W^T image [n][k] bf16 hi/lo, SW128-swizzled.
// block b: 0=Wn_g 1=Wn_d 2=W1[:128] 3=W1[128:]
// ---------------------------------------------------------------------------
__global__ __launch_bounds__(256) void wsplit_kernel(
    const float* __restrict__ Wg, const float* __restrict__ Wd,
    const float* __restrict__ W1)
{
    const float* W = (blockIdx.x == 0) ? Wg : (blockIdx.x == 1) ? Wd
                   : (blockIdx.x == 2) ? W1 : (W1 + CC * CC);
    int n = threadIdx.x >> 1;
    int c = threadIdx.x & 1;
    char* ph = (char*)&g_wimg[blockIdx.x][0][(size_t)c * CHUNK_ELEMS];
    char* pl = (char*)&g_wimg[blockIdx.x][1][(size_t)c * CHUNK_ELEMS];
    #pragma unroll
    for (int kk = 0; kk < 64; kk += 4) {
        int k = c * 64 + kk;
        float4 v = make_float4(W[(size_t)(k + 0) * CC + n], W[(size_t)(k + 1) * CC + n],
                               W[(size_t)(k + 2) * CC + n], W[(size_t)(k + 3) * CC + n]);
        uint2 hv, lv;
        split4(v, hv, lv);
        uint32_t off = swz((uint32_t)(n * 128 + kk * 2));
        *(uint2*)(ph + off) = hv;
        *(uint2*)(pl + off) = lv;
    }
}

// ---------------------------------------------------------------------------
// Fused 3-product split-bf16 MMA (Ah*Wh + Ah*Wl + Al*Wh in ONE k-loop).
// Warp tile 64x32: wm in 0..1 (64-row halves), wn in 0..3 (32-col quarters).
// Per kt: 12 LDSM.x4 -> 48 MMAs (ratio 0.25).
// ---------------------------------------------------------------------------
__device__ __forceinline__ void mma_stage(
    uint32_t abh, uint32_t abl, uint32_t bbh, uint32_t bbl,
    int wm, int wn, int lane, float acc[4][4][4])
{
    const int g = lane >> 3;
    const int r7 = lane & 7;
    const int arow = ((g & 1) << 3) + r7;
    const int akseg = (g >> 1) << 4;
    const int brow = ((g >> 1) << 3) + r7;
    const int bkseg = (g & 1) << 4;

    #pragma unroll
    for (int kt = 0; kt < 8; ++kt) {
        const uint32_t coff = (uint32_t)(kt >> 2) * 16384u;
        const int kb = (kt & 3) * 32;

        uint32_t ah[4][4], al[4][4];
        #pragma unroll
        for (int mt = 0; mt < 4; ++mt) {
            int row = wm * 64 + mt * 16 + arow;
            uint32_t so = coff + swz((uint32_t)(row * 128 + kb + akseg));
            LDSM_X4(ah[mt][0], ah[mt][1], ah[mt][2], ah[mt][3], abh + so);
            LDSM_X4(al[mt][0], al[mt][1], al[mt][2], al[mt][3], abl + so);
        }
        uint32_t wh[4][2], wl[4][2];
        #pragma unroll
        for (int h = 0; h < 2; ++h) {
            int n = wn * 32 + h * 16 + brow;
            uint32_t so = coff + swz((uint32_t)(n * 128 + kb + bkseg));
            uint32_t r0, r1, r2, r3;
            LDSM_X4(r0, r1, r2, r3, bbh + so);
            wh[h * 2][0] = r0;     wh[h * 2][1] = r1;
            wh[h * 2 + 1][0] = r2; wh[h * 2 + 1][1] = r3;
            LDSM_X4(r0, r1, r2, r3, bbl + so);
            wl[h * 2][0] = r0;     wl[h * 2][1] = r1;
            wl[h * 2 + 1][0] = r2; wl[h * 2 + 1][1] = r3;
        }
        #pragma unroll
        for (int mt = 0; mt < 4; ++mt)
            #pragma unroll
            for (int nt = 0; nt < 4; ++nt) {
                MMA16816(acc[mt][nt], ah[mt], wh[nt]);
                MMA16816(acc[mt][nt], ah[mt], wl[nt]);
                MMA16816(acc[mt][nt], al[mt], wh[nt]);
            }
    }
}

// ---------------------------------------------------------------------------
// Fused per-tile kernel (256 threads, 8 warps, 64x32 warp tiles):
//   z = relu(x@Wa + bias1) * mask ; u = z@Wb (+ bias2)
// blocks [0,TILES) = gene side, [TILES, 2*TILES) = disease side.
// ---------------------------------------------------------------------------
__global__ __launch_bounds__(256, 1) void fused_gemm_kernel(
    const float* __restrict__ Xg, const float* __restrict__ Xd,
    const float* __restrict__ bn_g, const float* __restrict__ bn_d,
    const float* __restrict__ b1,
    float* __restrict__ z_gen, float* __restrict__ z_dis)
{
    extern __shared__ char smem[];
    const uint32_t sb = smem_u32(smem);
    const int tid = threadIdx.x;
    const int lane = tid & 31;
    const int wid = tid >> 5;
    const int wm = wid >> 2;   // 2 m-halves (64 rows)
    const int wn = wid & 3;    // 4 n-quarters (32 cols)

    const bool sideB = (blockIdx.x >= TILES);
    const int t = sideB ? (blockIdx.x - TILES) : blockIdx.x;
    const float* X = sideB ? Xd : Xg;
    const float* bias1 = sideB ? bn_d : bn_g;
    const float* bias2 = sideB ? b1 : nullptr;
    const unsigned char* mask = sideB ? g_mask_d : g_mask_g;
    float* zout = sideB ? z_dis : z_gen;
    float* uout = sideB ? g_ud : g_ug;
    const __nv_bfloat16* w1h = g_wimg[sideB ? 1 : 0][0];
    const __nv_bfloat16* w1l = g_wimg[sideB ? 1 : 0][1];
    const __nv_bfloat16* w2h = g_wimg[sideB ? 3 : 2][0];
    const __nv_bfloat16* w2l = g_wimg[sideB ? 3 : 2][1];
    const int M = sideB ? NDN : NGN;
    const int rows_left = M - t * TM;

    // ---- stage x -> bf16 hi/lo swizzled images; copy W images ----
    {
        const float4* xs = (const float4*)(X + (size_t)t * TM * CC);
        #pragma unroll
        for (int i = 0; i < 16; ++i) {
            int q = i * 256 + tid;          // float4 index within tile
            int row = q >> 5;
            int kk = (q & 31) << 2;
            float4 v = (row < rows_left) ? xs[q] : make_float4(0.f, 0.f, 0.f, 0.f);
            uint2 hv, lv;
            split4(v, hv, lv);
            uint32_t off = (uint32_t)((kk >> 6) * 16384)
                         + swz((uint32_t)(row * 128 + (kk & 63) * 2));
            *(uint2*)(smem + SM_AH + off) = hv;
            *(uint2*)(smem + SM_AL + off) = lv;
        }
        const uint4* s[4] = {(const uint4*)w1h, (const uint4*)w1l,
                             (const uint4*)w2h, (const uint4*)w2l};
        uint4* d[4] = {(uint4*)(smem + SM_W1H), (uint4*)(smem + SM_W1L),
                       (uint4*)(smem + SM_W2H), (uint4*)(smem + SM_W2L)};
        #pragma unroll
        for (int bimg = 0; bimg < 4; ++bimg)
            #pragma unroll
            for (int i = 0; i < 8; ++i)
                d[bimg][i * 256 + tid] = s[bimg][i * 256 + tid];
    }
    __syncthreads();

    float acc[4][4][4];
    #pragma unroll
    for (int mt = 0; mt < 4; ++mt)
        #pragma unroll
        for (int nt = 0; nt < 4; ++nt)
            #pragma unroll
            for (int j = 0; j < 4; ++j) acc[mt][nt][j] = 0.0f;

    // ---- stage 1: z = x @ Wa ----
    mma_stage(sb + SM_AH, sb + SM_AL, sb + SM_W1H, sb + SM_W1L, wm, wn, lane, acc);
    __syncthreads();   // everyone done reading A images before overwrite

    // ---- epilogue 1: bias + relu*mask, write z, re-split into A buffers ----
    const int row_base = t * TM;
    #pragma unroll
    for (int mt = 0; mt < 4; ++mt) {
        const int rl0 = wm * 64 + mt * 16 + (lane >> 2);
        #pragma unroll
        for (int nt = 0; nt < 4; ++nt) {
            const int col = wn * 32 + nt * 8 + 2 * (lane & 3);
            const float2 bv = *(const float2*)&bias1[col];
            #pragma unroll
            for (int hh = 0; hh < 2; ++hh) {
                const int rl = rl0 + hh * 8;
                const int r = row_base + rl;
                float v0 = acc[mt][nt][hh * 2 + 0] + bv.x;
                float v1 = acc[mt][nt][hh * 2 + 1] + bv.y;
                if (r < M) {
                    const float mmv = (float)mask[r];
                    v0 = fmaxf(v0, 0.0f) * mmv;
                    v1 = fmaxf(v1, 0.0f) * mmv;
                    *(float2*)(zout + (size_t)r * CC + col) = make_float2(v0, v1);
                    uint32_t h, l;
                    split2(v0, v1, h, l);
                    uint32_t off = (uint32_t)((col >> 6) * 16384)
                                 + swz((uint32_t)(rl * 128 + (col & 63) * 2));
                    *(uint32_t*)(smem + SM_AH + off) = h;
                    *(uint32_t*)(smem + SM_AL + off) = l;
                }
            }
        }
    }
    __syncthreads();

    // ---- stage 2: u = z @ Wb ----
    #pragma unroll
    for (int mt = 0; mt < 4; ++mt)
        #pragma unroll
        for (int nt = 0; nt < 4; ++nt)
            #pragma unroll
            for (int j = 0; j < 4; ++j) acc[mt][nt][j] = 0.0f;

    mma_stage(sb + SM_AH, sb + SM_AL, sb + SM_W2H, sb + SM_W2L, wm, wn, lane, acc);

    // ---- epilogue 2: (+bias2), write u ----
    #pragma unroll
    for (int mt = 0; mt < 4; ++mt) {
        const int rl0 = wm * 64 + mt * 16 + (lane >> 2);
        #pragma unroll
        for (int nt = 0; nt < 4; ++nt) {
            const int col = wn * 32 + nt * 8 + 2 * (lane & 3);
            float2 bv = bias2 ? *(const float2*)&bias2[col] : make_float2(0.f, 0.f);
            #pragma unroll
            for (int hh = 0; hh < 2; ++hh) {
                const int r = row_base + rl0 + hh * 8;
                if (r < M) {
                    float v0 = acc[mt][nt][hh * 2 + 0] + bv.x;
                    float v1 = acc[mt][nt][hh * 2 + 1] + bv.y;
                    *(float2*)(uout + (size_t)r * CC + col) = make_float2(v0, v1);
                }
            }
        }
    }
}

// ---------------------------------------------------------------------------
// Link prediction head: one warp per labeled edge.
// ---------------------------------------------------------------------------
__global__ __launch_bounds__(256) void pred_kernel(
    const int* __restrict__ erow, const int* __restrict__ ecol,
    const float* __restrict__ W2, const float* __restrict__ b2,
    float* __restrict__ pred)
{
    int warp = (blockIdx.x * blockDim.x + threadIdx.x) >> 5;
    int lane = threadIdx.x & 31;
    if (warp >= NEL) return;

    int r = erow[warp];
    int c = ecol[warp];
    const float4 ug = *(const float4*)(g_ug + (size_t)r * CC + lane * 4);
    const float4 ud = *(const float4*)(g_ud + (size_t)c * CC + lane * 4);
    const float4 w2 = *(const float4*)(W2 + lane * 4);

    float s = fmaxf(ug.x + ud.x, 0.f) * w2.x
            + fmaxf(ug.y + ud.y, 0.f) * w2.y
            + fmaxf(ug.z + ud.z, 0.f) * w2.z
            + fmaxf(ug.w + ud.w, 0.f) * w2.w;

    #pragma unroll
    for (int o = 16; o > 0; o >>= 1)
        s += __shfl_xor_sync(0xFFFFFFFFu, s, o);

    if (lane == 0) pred[warp] = s + b2[0];
}

// ---------------------------------------------------------------------------
extern "C" void kernel_launch(void* const* d_in, const int* in_sizes, int n_in,
                              void* d_out, int out_size)
{
    (void)in_sizes; (void)n_in; (void)out_size;

    const float* x_gene    = (const float*)d_in[0];
    const float* x_disease = (const float*)d_in[1];
    const int*   ei_g2d    = (const int*)d_in[2];
    const int*   ei_d2g    = (const int*)d_in[3];
    const int*   eli       = (const int*)d_in[6];
    const float* Wn_g      = (const float*)d_in[7];
    const float* bn_g      = (const float*)d_in[8];
    const float* Wn_d      = (const float*)d_in[9];
    const float* bn_d      = (const float*)d_in[10];
    const float* W1        = (const float*)d_in[17];
    const float* b1        = (const float*)d_in[18];
    const float* W2        = (const float*)d_in[19];
    const float* b2        = (const float*)d_in[20];

    float* out   = (float*)d_out;
    float* pred  = out;
    float* z_gen = out + NEL;
    float* z_dis = out + NEL + (size_t)NGN * CC;

    cudaFuncSetAttribute(fused_gemm_kernel,
                         cudaFuncAttributeMaxDynamicSharedMemorySize, SMEM_TOTAL);

    // 1) isolation masks
    init_masks_kernel<<<(NGN + 255) / 256, 256>>>();
    scatter_masks_kernel<<<(NE + 255) / 256, 256>>>(ei_g2d + NE, ei_d2g + NE);

    // 2) weight split images (4 x 32KB hi + 32KB lo, swizzled W^T)
    wsplit_kernel<<<4, 256>>>(Wn_g, Wn_d, W1);

    // 3) fused (z, u) for both node types in one grid
    fused_gemm_kernel<<<2 * TILES, 256, SMEM_TOTAL>>>(
        x_gene, x_disease, bn_g, bn_d, b1, z_gen, z_dis);

    // 4) edge scores
    pred_kernel<<<(NEL * 32 + 255) / 256, 256>>>(eli, eli + NEL, W2, b2, pred);
}

// round 10
// speedup vs baseline: 1.5203x; 1.0049x over previous
#include <cuda_runtime.h>
#include <cuda_bf16.h>
#include <cstdint>
#include <cstddef>

#define NGN 100000
#define NDN 100000
#define NE  400000
#define NEL 200000
#define CC  128
#define TM  128
#define TILES ((NGN + TM - 1) / TM)      // 782
#define CHUNK_ELEMS 8192                 // 128 rows * 64 bf16 = 16KB
#define TILE_IMG_ELEMS (2 * CHUNK_ELEMS) // 32KB image (2 chunks)

// smem layout (bytes): A-hi, A-lo (reused for Z-hi/Z-lo), W1 hi/lo, W2 hi/lo
#define SM_AH   0
#define SM_AL   32768
#define SM_W1H  65536
#define SM_W1L  98304
#define SM_W2H  131072
#define SM_W2L  163840
#define SMEM_TOTAL 196608

// ---------------------------------------------------------------------------
__device__ __align__(16) __nv_bfloat16 g_wimg[4][2][TILE_IMG_ELEMS]; // [mat][hi/lo]
__device__ __align__(16) float g_ug[(size_t)NGN * CC];
__device__ __align__(16) float g_ud[(size_t)NDN * CC];
__device__ unsigned char g_mask_g[NGN];
__device__ unsigned char g_mask_d[NDN];

// ---------------------------------------------------------------------------
__device__ __forceinline__ uint32_t smem_u32(const void* p) {
    uint32_t a;
    asm("{ .reg .u64 t; cvta.to.shared.u64 t, %1; cvt.u32.u64 %0, t; }"
        : "=r"(a) : "l"(p));
    return a;
}
__device__ __forceinline__ uint32_t swz(uint32_t off) {   // SW128 swizzle
    return off ^ ((off >> 3) & 0x70);
}

#define LDSM_X4(r0, r1, r2, r3, addr) \
    asm volatile("ldmatrix.sync.aligned.m8n8.x4.shared.b16 {%0,%1,%2,%3}, [%4];" \
        : "=r"(r0), "=r"(r1), "=r"(r2), "=r"(r3) : "r"(addr))

#define MMA16816(c, a, b) \
    asm volatile("mma.sync.aligned.m16n8k16.row.col.f32.bf16.bf16.f32 " \
        "{%0,%1,%2,%3}, {%4,%5,%6,%7}, {%8,%9}, {%0,%1,%2,%3};" \
        : "+f"((c)[0]), "+f"((c)[1]), "+f"((c)[2]), "+f"((c)[3]) \
        : "r"((a)[0]), "r"((a)[1]), "r"((a)[2]), "r"((a)[3]), \
          "r"((b)[0]), "r"((b)[1]))

// split fp32 -> bf16 hi + bf16 lo (residual)
__device__ __forceinline__ void split4(const float4 v, uint2& hv, uint2& lv) {
    __nv_bfloat16 h0 = __float2bfloat16(v.x), h1 = __float2bfloat16(v.y);
    __nv_bfloat16 h2 = __float2bfloat16(v.z), h3 = __float2bfloat16(v.w);
    float l0 = v.x - __bfloat162float(h0), l1 = v.y - __bfloat162float(h1);
    float l2 = v.z - __bfloat162float(h2), l3 = v.w - __bfloat162float(h3);
    __nv_bfloat162 hp0(h0, h1), hp1(h2, h3);
    __nv_bfloat162 lp0(__float2bfloat16(l0), __float2bfloat16(l1));
    __nv_bfloat162 lp1(__float2bfloat16(l2), __float2bfloat16(l3));
    hv.x = *(uint32_t*)&hp0; hv.y = *(uint32_t*)&hp1;
    lv.x = *(uint32_t*)&lp0; lv.y = *(uint32_t*)&lp1;
}
__device__ __forceinline__ void split2(float v0, float v1, uint32_t& h, uint32_t& l) {
    __nv_bfloat16 h0 = __float2bfloat16(v0), h1 = __float2bfloat16(v1);
    float l0 = v0 - __bfloat162float(h0), l1 = v1 - __bfloat162float(h1);
    __nv_bfloat162 hp(h0, h1);
    __nv_bfloat162 lp(__float2bfloat16(l0), __float2bfloat16(l1));
    h = *(uint32_t*)&hp; l = *(uint32_t*)&lp;
}

// ---------------------------------------------------------------------------
__global__ void init_masks_kernel() {
    int i = blockIdx.x * blockDim.x + threadIdx.x;
    if (i < NGN) g_mask_g[i] = 0;
    if (i < NDN) g_mask_d[i] = 0;
}
__global__ void scatter_masks_kernel(const int* __restrict__ dst_g2d,
                                     const int* __restrict__ dst_d2g) {
    int e = blockIdx.x * blockDim.x + threadIdx.x;
    if (e < NE) {
        g_mask_d[dst_g2d[e]] = 1;
        g_mask_g[dst_d2g[e]] = 1;
    }
}

// ---------------------------------------------------------------------------
// W split: W[128,128] (K x N) -> W^T image [n][k] bf16 hi/lo, SW128-swizzled.
// block b: 0=Wn_g 1=Wn_d 2=W1[:128] 3=W1[128:]
// ---------------------------------------------------------------------------
__global__ __launch_bounds__(256) void wsplit_kernel(
    const float* __restrict__ Wg, const float* __restrict__ Wd,
    const float* __restrict__ W1)
{
    const float* W = (blockIdx.x == 0) ? Wg : (blockIdx.x == 1) ? Wd
                   : (blockIdx.x == 2) ? W1 : (W1 + CC * CC);
    int n = threadIdx.x >> 1;
    int c = threadIdx.x & 1;
    char* ph = (char*)&g_wimg[blockIdx.x][0][(size_t)c * CHUNK_ELEMS];
    char* pl = (char*)&g_wimg[blockIdx.x][1][(size_t)c * CHUNK_ELEMS];
    #pragma unroll
    for (int kk = 0; kk < 64; kk += 4) {
        int k = c * 64 + kk;
        float4 v = make_float4(W[(size_t)(k + 0) * CC + n], W[(size_t)(k + 1) * CC + n],
                               W[(size_t)(k + 2) * CC + n], W[(size_t)(k + 3) * CC + n]);
        uint2 hv, lv;
        split4(v, hv, lv);
        uint32_t off = swz((uint32_t)(n * 128 + kk * 2));
        *(uint2*)(ph + off) = hv;
        *(uint2*)(pl + off) = lv;
    }
}

// ---------------------------------------------------------------------------
// Fused 3-product split-bf16 MMA, product index OUTER so the 16 independent
// accumulators sit between consecutive writes to the same acc (ILP for HMMA).
// Warp tile 64x32: per kt, 12 LDSM.x4 -> 48 MMAs.
// ---------------------------------------------------------------------------
__device__ __forceinline__ void mma_stage(
    uint32_t abh, uint32_t abl, uint32_t bbh, uint32_t bbl,
    int wm, int wn, int lane, float acc[4][4][4])
{
    const int g = lane >> 3;
    const int r7 = lane & 7;
    const int arow = ((g & 1) << 3) + r7;
    const int akseg = (g >> 1) << 4;
    const int brow = ((g >> 1) << 3) + r7;
    const int bkseg = (g & 1) << 4;

    #pragma unroll
    for (int kt = 0; kt < 8; ++kt) {
        const uint32_t coff = (uint32_t)(kt >> 2) * 16384u;
        const int kb = (kt & 3) * 32;

        uint32_t ah[4][4], al[4][4];
        #pragma unroll
        for (int mt = 0; mt < 4; ++mt) {
            int row = wm * 64 + mt * 16 + arow;
            uint32_t so = coff + swz((uint32_t)(row * 128 + kb + akseg));
            LDSM_X4(ah[mt][0], ah[mt][1], ah[mt][2], ah[mt][3], abh + so);
            LDSM_X4(al[mt][0], al[mt][1], al[mt][2], al[mt][3], abl + so);
        }
        uint32_t wh[4][2], wl[4][2];
        #pragma unroll
        for (int h = 0; h < 2; ++h) {
            int n = wn * 32 + h * 16 + brow;
            uint32_t so = coff + swz((uint32_t)(n * 128 + kb + bkseg));
            uint32_t r0, r1, r2, r3;
            LDSM_X4(r0, r1, r2, r3, bbh + so);
            wh[h * 2][0] = r0;     wh[h * 2][1] = r1;
            wh[h * 2 + 1][0] = r2; wh[h * 2 + 1][1] = r3;
            LDSM_X4(r0, r1, r2, r3, bbl + so);
            wl[h * 2][0] = r0;     wl[h * 2][1] = r1;
            wl[h * 2 + 1][0] = r2; wl[h * 2 + 1][1] = r3;
        }
        // product-outer order: 16 independent MMAs between acc reuse
        #pragma unroll
        for (int p = 0; p < 3; ++p)
            #pragma unroll
            for (int mt = 0; mt < 4; ++mt)
                #pragma unroll
                for (int nt = 0; nt < 4; ++nt)
                    MMA16816(acc[mt][nt],
                             (p == 2) ? al[mt] : ah[mt],
                             (p == 1) ? wl[nt] : wh[nt]);
    }
}

// ---------------------------------------------------------------------------
// Fused per-tile kernel (256 threads, 8 warps, 64x32 warp tiles):
//   z = relu(x@Wa + bias1) * mask ; u = z@Wb (+ bias2)
// blocks [0,TILES) = gene side, [TILES, 2*TILES) = disease side.
// ---------------------------------------------------------------------------
__global__ __launch_bounds__(256, 1) void fused_gemm_kernel(
    const float* __restrict__ Xg, const float* __restrict__ Xd,
    const float* __restrict__ bn_g, const float* __restrict__ bn_d,
    const float* __restrict__ b1,
    float* __restrict__ z_gen, float* __restrict__ z_dis)
{
    extern __shared__ char smem[];
    const uint32_t sb = smem_u32(smem);
    const int tid = threadIdx.x;
    const int lane = tid & 31;
    const int wid = tid >> 5;
    const int wm = wid >> 2;   // 2 m-halves (64 rows)
    const int wn = wid & 3;    // 4 n-quarters (32 cols)

    const bool sideB = (blockIdx.x >= TILES);
    const int t = sideB ? (blockIdx.x - TILES) : blockIdx.x;
    const float* X = sideB ? Xd : Xg;
    const float* bias1 = sideB ? bn_d : bn_g;
    const float* bias2 = sideB ? b1 : nullptr;
    const unsigned char* mask = sideB ? g_mask_d : g_mask_g;
    float* zout = sideB ? z_dis : z_gen;
    float* uout = sideB ? g_ud : g_ug;
    const __nv_bfloat16* w1h = g_wimg[sideB ? 1 : 0][0];
    const __nv_bfloat16* w1l = g_wimg[sideB ? 1 : 0][1];
    const __nv_bfloat16* w2h = g_wimg[sideB ? 3 : 2][0];
    const __nv_bfloat16* w2l = g_wimg[sideB ? 3 : 2][1];
    const int M = sideB ? NDN : NGN;
    const int rows_left = M - t * TM;

    // ---- stage x -> bf16 hi/lo swizzled images; copy W images ----
    {
        const float4* xs = (const float4*)(X + (size_t)t * TM * CC);
        #pragma unroll
        for (int i = 0; i < 16; ++i) {
            int q = i * 256 + tid;          // float4 index within tile
            int row = q >> 5;
            int kk = (q & 31) << 2;
            float4 v = (row < rows_left) ? xs[q] : make_float4(0.f, 0.f, 0.f, 0.f);
            uint2 hv, lv;
            split4(v, hv, lv);
            uint32_t off = (uint32_t)((kk >> 6) * 16384)
                         + swz((uint32_t)(row * 128 + (kk & 63) * 2));
            *(uint2*)(smem + SM_AH + off) = hv;
            *(uint2*)(smem + SM_AL + off) = lv;
        }
        const uint4* s[4] = {(const uint4*)w1h, (const uint4*)w1l,
                             (const uint4*)w2h, (const uint4*)w2l};
        uint4* d[4] = {(uint4*)(smem + SM_W1H), (uint4*)(smem + SM_W1L),
                       (uint4*)(smem + SM_W2H), (uint4*)(smem + SM_W2L)};
        #pragma unroll
        for (int bimg = 0; bimg < 4; ++bimg)
            #pragma unroll
            for (int i = 0; i < 8; ++i)
                d[bimg][i * 256 + tid] = s[bimg][i * 256 + tid];
    }
    __syncthreads();

    float acc[4][4][4];
    #pragma unroll
    for (int mt = 0; mt < 4; ++mt)
        #pragma unroll
        for (int nt = 0; nt < 4; ++nt)
            #pragma unroll
            for (int j = 0; j < 4; ++j) acc[mt][nt][j] = 0.0f;

    // ---- stage 1: z = x @ Wa ----
    mma_stage(sb + SM_AH, sb + SM_AL, sb + SM_W1H, sb + SM_W1L, wm, wn, lane, acc);
    __syncthreads();   // everyone done reading A images before overwrite

    // ---- epilogue 1: bias + relu*mask, write z, re-split into A buffers ----
    const int row_base = t * TM;
    #pragma unroll
    for (int mt = 0; mt < 4; ++mt) {
        const int rl0 = wm * 64 + mt * 16 + (lane >> 2);
        #pragma unroll
        for (int nt = 0; nt < 4; ++nt) {
            const int col = wn * 32 + nt * 8 + 2 * (lane & 3);
            const float2 bv = *(const float2*)&bias1[col];
            #pragma unroll
            for (int hh = 0; hh < 2; ++hh) {
                const int rl = rl0 + hh * 8;
                const int r = row_base + rl;
                float v0 = acc[mt][nt][hh * 2 + 0] + bv.x;
                float v1 = acc[mt][nt][hh * 2 + 1] + bv.y;
                if (r < M) {
                    const float mmv = (float)mask[r];
                    v0 = fmaxf(v0, 0.0f) * mmv;
                    v1 = fmaxf(v1, 0.0f) * mmv;
                    *(float2*)(zout + (size_t)r * CC + col) = make_float2(v0, v1);
                    uint32_t h, l;
                    split2(v0, v1, h, l);
                    uint32_t off = (uint32_t)((col >> 6) * 16384)
                                 + swz((uint32_t)(rl * 128 + (col & 63) * 2));
                    *(uint32_t*)(smem + SM_AH + off) = h;
                    *(uint32_t*)(smem + SM_AL + off) = l;
                }
            }
        }
    }
    __syncthreads();

    // ---- stage 2: u = z @ Wb ----
    #pragma unroll
    for (int mt = 0; mt < 4; ++mt)
        #pragma unroll
        for (int nt = 0; nt < 4; ++nt)
            #pragma unroll
            for (int j = 0; j < 4; ++j) acc[mt][nt][j] = 0.0f;

    mma_stage(sb + SM_AH, sb + SM_AL, sb + SM_W2H, sb + SM_W2L, wm, wn, lane, acc);

    // ---- epilogue 2: (+bias2), write u ----
    #pragma unroll
    for (int mt = 0; mt < 4; ++mt) {
        const int rl0 = wm * 64 + mt * 16 + (lane >> 2);
        #pragma unroll
        for (int nt = 0; nt < 4; ++nt) {
            const int col = wn * 32 + nt * 8 + 2 * (lane & 3);
            float2 bv = bias2 ? *(const float2*)&bias2[col] : make_float2(0.f, 0.f);
            #pragma unroll
            for (int hh = 0; hh < 2; ++hh) {
                const int r = row_base + rl0 + hh * 8;
                if (r < M) {
                    float v0 = acc[mt][nt][hh * 2 + 0] + bv.x;
                    float v1 = acc[mt][nt][hh * 2 + 1] + bv.y;
                    *(float2*)(uout + (size_t)r * CC + col) = make_float2(v0, v1);
                }
            }
        }
    }
}

// ---------------------------------------------------------------------------
// Link prediction head: one warp per labeled edge.
// ---------------------------------------------------------------------------
__global__ __launch_bounds__(256) void pred_kernel(
    const int* __restrict__ erow, const int* __restrict__ ecol,
    const float* __restrict__ W2, const float* __restrict__ b2,
    float* __restrict__ pred)
{
    int warp = (blockIdx.x * blockDim.x + threadIdx.x) >> 5;
    int lane = threadIdx.x & 31;
    if (warp >= NEL) return;

    int r = erow[warp];
    int c = ecol[warp];
    const float4 ug = *(const float4*)(g_ug + (size_t)r * CC + lane * 4);
    const float4 ud = *(const float4*)(g_ud + (size_t)c * CC + lane * 4);
    const float4 w2 = *(const float4*)(W2 + lane * 4);

    float s = fmaxf(ug.x + ud.x, 0.f) * w2.x
            + fmaxf(ug.y + ud.y, 0.f) * w2.y
            + fmaxf(ug.z + ud.z, 0.f) * w2.z
            + fmaxf(ug.w + ud.w, 0.f) * w2.w;

    #pragma unroll
    for (int o = 16; o > 0; o >>= 1)
        s += __shfl_xor_sync(0xFFFFFFFFu, s, o);

    if (lane == 0) pred[warp] = s + b2[0];
}

// ---------------------------------------------------------------------------
extern "C" void kernel_launch(void* const* d_in, const int* in_sizes, int n_in,
                              void* d_out, int out_size)
{
    (void)in_sizes; (void)n_in; (void)out_size;

    const float* x_gene    = (const float*)d_in[0];
    const float* x_disease = (const float*)d_in[1];
    const int*   ei_g2d    = (const int*)d_in[2];
    const int*   ei_d2g    = (const int*)d_in[3];
    const int*   eli       = (const int*)d_in[6];
    const float* Wn_g      = (const float*)d_in[7];
    const float* bn_g      = (const float*)d_in[8];
    const float* Wn_d      = (const float*)d_in[9];
    const float* bn_d      = (const float*)d_in[10];
    const float* W1        = (const float*)d_in[17];
    const float* b1        = (const float*)d_in[18];
    const float* W2        = (const float*)d_in[19];
    const float* b2        = (const float*)d_in[20];

    float* out   = (float*)d_out;
    float* pred  = out;
    float* z_gen = out + NEL;
    float* z_dis = out + NEL + (size_t)NGN * CC;

    cudaFuncSetAttribute(fused_gemm_kernel,
                         cudaFuncAttributeMaxDynamicSharedMemorySize, SMEM_TOTAL);

    // 1) isolation masks
    init_masks_kernel<<<(NGN + 255) / 256, 256>>>();
    scatter_masks_kernel<<<(NE + 255) / 256, 256>>>(ei_g2d + NE, ei_d2g + NE);

    // 2) weight split images (4 x 32KB hi + 32KB lo, swizzled W^T)
    wsplit_kernel<<<4, 256>>>(Wn_g, Wn_d, W1);

    // 3) fused (z, u) for both node types in one grid
    fused_gemm_kernel<<<2 * TILES, 256, SMEM_TOTAL>>>(
        x_gene, x_disease, bn_g, bn_d, b1, z_gen, z_dis);

    // 4) edge scores
    pred_kernel<<<(NEL * 32 + 255) / 256, 256>>>(eli, eli + NEL, W2, b2, pred);
}

// round 11
// speedup vs baseline: 1.5635x; 1.0284x over previous
#include <cuda_runtime.h>
#include <cuda_bf16.h>
#include <cstdint>
#include <cstddef>

#define NGN 100000
#define NDN 100000
#define NE  400000
#define NEL 200000
#define CC  128
#define TM  128
#define TILES ((NGN + TM - 1) / TM)      // 782
#define CHUNK_ELEMS 8192                 // 128 rows * 64 bf16 = 16KB
#define TILE_IMG_ELEMS (2 * CHUNK_ELEMS) // 32KB image (2 chunks)

// smem layout (bytes): A-hi, A-lo (reused for Z-hi/Z-lo), W1 hi/lo, W2 hi/lo
#define SM_AH   0
#define SM_AL   32768
#define SM_W1H  65536
#define SM_W1L  98304
#define SM_W2H  131072
#define SM_W2L  163840
#define SMEM_TOTAL 196608

// ---------------------------------------------------------------------------
__device__ __align__(16) __nv_bfloat16 g_wimg[4][2][TILE_IMG_ELEMS]; // [mat][hi/lo]
__device__ __align__(16) float g_ug[(size_t)NGN * CC];
__device__ __align__(16) float g_ud[(size_t)NDN * CC];
__device__ unsigned char g_mask_g[NGN];
__device__ unsigned char g_mask_d[NDN];

// ---------------------------------------------------------------------------
__device__ __forceinline__ uint32_t smem_u32(const void* p) {
    uint32_t a;
    asm("{ .reg .u64 t; cvta.to.shared.u64 t, %1; cvt.u32.u64 %0, t; }"
        : "=r"(a) : "l"(p));
    return a;
}
__device__ __forceinline__ uint32_t swz(uint32_t off) {   // SW128 swizzle
    return off ^ ((off >> 3) & 0x70);
}

#define LDSM_X4(r0, r1, r2, r3, addr) \
    asm volatile("ldmatrix.sync.aligned.m8n8.x4.shared.b16 {%0,%1,%2,%3}, [%4];" \
        : "=r"(r0), "=r"(r1), "=r"(r2), "=r"(r3) : "r"(addr))

#define MMA16816(c, a, b) \
    asm volatile("mma.sync.aligned.m16n8k16.row.col.f32.bf16.bf16.f32 " \
        "{%0,%1,%2,%3}, {%4,%5,%6,%7}, {%8,%9}, {%0,%1,%2,%3};" \
        : "+f"((c)[0]), "+f"((c)[1]), "+f"((c)[2]), "+f"((c)[3]) \
        : "r"((a)[0]), "r"((a)[1]), "r"((a)[2]), "r"((a)[3]), \
          "r"((b)[0]), "r"((b)[1]))

// split fp32 -> bf16 hi + bf16 lo (residual)
__device__ __forceinline__ void split4(const float4 v, uint2& hv, uint2& lv) {
    __nv_bfloat16 h0 = __float2bfloat16(v.x), h1 = __float2bfloat16(v.y);
    __nv_bfloat16 h2 = __float2bfloat16(v.z), h3 = __float2bfloat16(v.w);
    float l0 = v.x - __bfloat162float(h0), l1 = v.y - __bfloat162float(h1);
    float l2 = v.z - __bfloat162float(h2), l3 = v.w - __bfloat162float(h3);
    __nv_bfloat162 hp0(h0, h1), hp1(h2, h3);
    __nv_bfloat162 lp0(__float2bfloat16(l0), __float2bfloat16(l1));
    __nv_bfloat162 lp1(__float2bfloat16(l2), __float2bfloat16(l3));
    hv.x = *(uint32_t*)&hp0; hv.y = *(uint32_t*)&hp1;
    lv.x = *(uint32_t*)&lp0; lv.y = *(uint32_t*)&lp1;
}
__device__ __forceinline__ void split2(float v0, float v1, uint32_t& h, uint32_t& l) {
    __nv_bfloat16 h0 = __float2bfloat16(v0), h1 = __float2bfloat16(v1);
    float l0 = v0 - __bfloat162float(h0), l1 = v1 - __bfloat162float(h1);
    __nv_bfloat162 hp(h0, h1);
    __nv_bfloat162 lp(__float2bfloat16(l0), __float2bfloat16(l1));
    h = *(uint32_t*)&hp; l = *(uint32_t*)&lp;
}

// ---------------------------------------------------------------------------
__global__ void init_masks_kernel() {
    int i = blockIdx.x * blockDim.x + threadIdx.x;
    if (i < NGN) g_mask_g[i] = 0;
    if (i < NDN) g_mask_d[i] = 0;
}
__global__ void scatter_masks_kernel(const int* __restrict__ dst_g2d,
                                     const int* __restrict__ dst_d2g) {
    int e = blockIdx.x * blockDim.x + threadIdx.x;
    if (e < NE) {
        g_mask_d[dst_g2d[e]] = 1;
        g_mask_g[dst_d2g[e]] = 1;
    }
}

// ---------------------------------------------------------------------------
// W split: W[128,128] (K x N) -> W^T image [n][k] bf16 hi/lo, SW128-swizzled.
// block b: 0=Wn_g 1=Wn_d 2=W1[:128] 3=W1[128:]
// ---------------------------------------------------------------------------
__global__ __launch_bounds__(256) void wsplit_kernel(
    const float* __restrict__ Wg, const float* __restrict__ Wd,
    const float* __restrict__ W1)
{
    const float* W = (blockIdx.x == 0) ? Wg : (blockIdx.x == 1) ? Wd
                   : (blockIdx.x == 2) ? W1 : (W1 + CC * CC);
    int n = threadIdx.x >> 1;
    int c = threadIdx.x & 1;
    char* ph = (char*)&g_wimg[blockIdx.x][0][(size_t)c * CHUNK_ELEMS];
    char* pl = (char*)&g_wimg[blockIdx.x][1][(size_t)c * CHUNK_ELEMS];
    #pragma unroll
    for (int kk = 0; kk < 64; kk += 4) {
        int k = c * 64 + kk;
        float4 v = make_float4(W[(size_t)(k + 0) * CC + n], W[(size_t)(k + 1) * CC + n],
                               W[(size_t)(k + 2) * CC + n], W[(size_t)(k + 3) * CC + n]);
        uint2 hv, lv;
        split4(v, hv, lv);
        uint32_t off = swz((uint32_t)(n * 128 + kk * 2));
        *(uint2*)(ph + off) = hv;
        *(uint2*)(pl + off) = lv;
    }
}

// ---------------------------------------------------------------------------
// Fused 3-product split-bf16 MMA (Ah*Wh + Ah*Wl + Al*Wh in one k-loop).
// Warp tile 32x32: wm in 0..3 (32-row quarters), wn in 0..3 (32-col quarters).
// Per kt: 8 LDSM.x4 -> 24 MMAs (ratio 0.33).
// ---------------------------------------------------------------------------
__device__ __forceinline__ void mma_stage(
    uint32_t abh, uint32_t abl, uint32_t bbh, uint32_t bbl,
    int wm, int wn, int lane, float acc[2][4][4])
{
    const int g = lane >> 3;
    const int r7 = lane & 7;
    const int arow = ((g & 1) << 3) + r7;
    const int akseg = (g >> 1) << 4;
    const int brow = ((g >> 1) << 3) + r7;
    const int bkseg = (g & 1) << 4;

    #pragma unroll
    for (int kt = 0; kt < 8; ++kt) {
        const uint32_t coff = (uint32_t)(kt >> 2) * 16384u;
        const int kb = (kt & 3) * 32;

        uint32_t ah[2][4], al[2][4];
        #pragma unroll
        for (int mt = 0; mt < 2; ++mt) {
            int row = wm * 32 + mt * 16 + arow;
            uint32_t so = coff + swz((uint32_t)(row * 128 + kb + akseg));
            LDSM_X4(ah[mt][0], ah[mt][1], ah[mt][2], ah[mt][3], abh + so);
            LDSM_X4(al[mt][0], al[mt][1], al[mt][2], al[mt][3], abl + so);
        }
        uint32_t wh[4][2], wl[4][2];
        #pragma unroll
        for (int h = 0; h < 2; ++h) {
            int n = wn * 32 + h * 16 + brow;
            uint32_t so = coff + swz((uint32_t)(n * 128 + kb + bkseg));
            uint32_t r0, r1, r2, r3;
            LDSM_X4(r0, r1, r2, r3, bbh + so);
            wh[h * 2][0] = r0;     wh[h * 2][1] = r1;
            wh[h * 2 + 1][0] = r2; wh[h * 2 + 1][1] = r3;
            LDSM_X4(r0, r1, r2, r3, bbl + so);
            wl[h * 2][0] = r0;     wl[h * 2][1] = r1;
            wl[h * 2 + 1][0] = r2; wl[h * 2 + 1][1] = r3;
        }
        #pragma unroll
        for (int p = 0; p < 3; ++p)
            #pragma unroll
            for (int mt = 0; mt < 2; ++mt)
                #pragma unroll
                for (int nt = 0; nt < 4; ++nt)
                    MMA16816(acc[mt][nt],
                             (p == 2) ? al[mt] : ah[mt],
                             (p == 1) ? wl[nt] : wh[nt]);
    }
}

// ---------------------------------------------------------------------------
// Fused per-tile kernel (512 threads, 16 warps, 32x32 warp tiles):
//   z = relu(x@Wa + bias1) * mask ; u = z@Wb (+ bias2)
// blocks [0,TILES) = gene side, [TILES, 2*TILES) = disease side.
// ---------------------------------------------------------------------------
__global__ __launch_bounds__(512, 1) void fused_gemm_kernel(
    const float* __restrict__ Xg, const float* __restrict__ Xd,
    const float* __restrict__ bn_g, const float* __restrict__ bn_d,
    const float* __restrict__ b1,
    float* __restrict__ z_gen, float* __restrict__ z_dis)
{
    extern __shared__ char smem[];
    const uint32_t sb = smem_u32(smem);
    const int tid = threadIdx.x;
    const int lane = tid & 31;
    const int wid = tid >> 5;
    const int wm = wid >> 2;   // 4 m-quarters (32 rows)
    const int wn = wid & 3;    // 4 n-quarters (32 cols)

    const bool sideB = (blockIdx.x >= TILES);
    const int t = sideB ? (blockIdx.x - TILES) : blockIdx.x;
    const float* X = sideB ? Xd : Xg;
    const float* bias1 = sideB ? bn_d : bn_g;
    const float* bias2 = sideB ? b1 : nullptr;
    const unsigned char* mask = sideB ? g_mask_d : g_mask_g;
    float* zout = sideB ? z_dis : z_gen;
    float* uout = sideB ? g_ud : g_ug;
    const __nv_bfloat16* w1h = g_wimg[sideB ? 1 : 0][0];
    const __nv_bfloat16* w1l = g_wimg[sideB ? 1 : 0][1];
    const __nv_bfloat16* w2h = g_wimg[sideB ? 3 : 2][0];
    const __nv_bfloat16* w2l = g_wimg[sideB ? 3 : 2][1];
    const int M = sideB ? NDN : NGN;
    const int rows_left = M - t * TM;

    // ---- stage x -> bf16 hi/lo swizzled images; copy W images ----
    {
        const float4* xs = (const float4*)(X + (size_t)t * TM * CC);
        #pragma unroll
        for (int i = 0; i < 8; ++i) {
            int q = i * 512 + tid;          // float4 index within tile
            int row = q >> 5;
            int kk = (q & 31) << 2;
            float4 v = (row < rows_left) ? xs[q] : make_float4(0.f, 0.f, 0.f, 0.f);
            uint2 hv, lv;
            split4(v, hv, lv);
            uint32_t off = (uint32_t)((kk >> 6) * 16384)
                         + swz((uint32_t)(row * 128 + (kk & 63) * 2));
            *(uint2*)(smem + SM_AH + off) = hv;
            *(uint2*)(smem + SM_AL + off) = lv;
        }
        const uint4* s[4] = {(const uint4*)w1h, (const uint4*)w1l,
                             (const uint4*)w2h, (const uint4*)w2l};
        uint4* d[4] = {(uint4*)(smem + SM_W1H), (uint4*)(smem + SM_W1L),
                       (uint4*)(smem + SM_W2H), (uint4*)(smem + SM_W2L)};
        #pragma unroll
        for (int bimg = 0; bimg < 4; ++bimg)
            #pragma unroll
            for (int i = 0; i < 4; ++i)
                d[bimg][i * 512 + tid] = s[bimg][i * 512 + tid];
    }
    __syncthreads();

    float acc[2][4][4];
    #pragma unroll
    for (int mt = 0; mt < 2; ++mt)
        #pragma unroll
        for (int nt = 0; nt < 4; ++nt)
            #pragma unroll
            for (int j = 0; j < 4; ++j) acc[mt][nt][j] = 0.0f;

    // ---- stage 1: z = x @ Wa ----
    mma_stage(sb + SM_AH, sb + SM_AL, sb + SM_W1H, sb + SM_W1L, wm, wn, lane, acc);
    __syncthreads();   // everyone done reading A images before overwrite

    // ---- epilogue 1: bias + relu*mask, write z, re-split into A buffers ----
    const int row_base = t * TM;
    #pragma unroll
    for (int mt = 0; mt < 2; ++mt) {
        const int rl0 = wm * 32 + mt * 16 + (lane >> 2);
        #pragma unroll
        for (int nt = 0; nt < 4; ++nt) {
            const int col = wn * 32 + nt * 8 + 2 * (lane & 3);
            const float2 bv = *(const float2*)&bias1[col];
            #pragma unroll
            for (int hh = 0; hh < 2; ++hh) {
                const int rl = rl0 + hh * 8;
                const int r = row_base + rl;
                float v0 = acc[mt][nt][hh * 2 + 0] + bv.x;
                float v1 = acc[mt][nt][hh * 2 + 1] + bv.y;
                if (r < M) {
                    const float mmv = (float)mask[r];
                    v0 = fmaxf(v0, 0.0f) * mmv;
                    v1 = fmaxf(v1, 0.0f) * mmv;
                    *(float2*)(zout + (size_t)r * CC + col) = make_float2(v0, v1);
                    uint32_t h, l;
                    split2(v0, v1, h, l);
                    uint32_t off = (uint32_t)((col >> 6) * 16384)
                                 + swz((uint32_t)(rl * 128 + (col & 63) * 2));
                    *(uint32_t*)(smem + SM_AH + off) = h;
                    *(uint32_t*)(smem + SM_AL + off) = l;
                }
            }
        }
    }
    __syncthreads();

    // ---- stage 2: u = z @ Wb ----
    #pragma unroll
    for (int mt = 0; mt < 2; ++mt)
        #pragma unroll
        for (int nt = 0; nt < 4; ++nt)
            #pragma unroll
            for (int j = 0; j < 4; ++j) acc[mt][nt][j] = 0.0f;

    mma_stage(sb + SM_AH, sb + SM_AL, sb + SM_W2H, sb + SM_W2L, wm, wn, lane, acc);

    // ---- epilogue 2: (+bias2), write u ----
    #pragma unroll
    for (int mt = 0; mt < 2; ++mt) {
        const int rl0 = wm * 32 + mt * 16 + (lane >> 2);
        #pragma unroll
        for (int nt = 0; nt < 4; ++nt) {
            const int col = wn * 32 + nt * 8 + 2 * (lane & 3);
            float2 bv = bias2 ? *(const float2*)&bias2[col] : make_float2(0.f, 0.f);
            #pragma unroll
            for (int hh = 0; hh < 2; ++hh) {
                const int r = row_base + rl0 + hh * 8;
                if (r < M) {
                    float v0 = acc[mt][nt][hh * 2 + 0] + bv.x;
                    float v1 = acc[mt][nt][hh * 2 + 1] + bv.y;
                    *(float2*)(uout + (size_t)r * CC + col) = make_float2(v0, v1);
                }
            }
        }
    }
}

// ---------------------------------------------------------------------------
// Link prediction head: one warp per labeled edge.
// ---------------------------------------------------------------------------
__global__ __launch_bounds__(256) void pred_kernel(
    const int* __restrict__ erow, const int* __restrict__ ecol,
    const float* __restrict__ W2, const float* __restrict__ b2,
    float* __restrict__ pred)
{
    int warp = (blockIdx.x * blockDim.x + threadIdx.x) >> 5;
    int lane = threadIdx.x & 31;
    if (warp >= NEL) return;

    int r = erow[warp];
    int c = ecol[warp];
    const float4 ug = *(const float4*)(g_ug + (size_t)r * CC + lane * 4);
    const float4 ud = *(const float4*)(g_ud + (size_t)c * CC + lane * 4);
    const float4 w2 = *(const float4*)(W2 + lane * 4);

    float s = fmaxf(ug.x + ud.x, 0.f) * w2.x
            + fmaxf(ug.y + ud.y, 0.f) * w2.y
            + fmaxf(ug.z + ud.z, 0.f) * w2.z
            + fmaxf(ug.w + ud.w, 0.f) * w2.w;

    #pragma unroll
    for (int o = 16; o > 0; o >>= 1)
        s += __shfl_xor_sync(0xFFFFFFFFu, s, o);

    if (lane == 0) pred[warp] = s + b2[0];
}

// ---------------------------------------------------------------------------
extern "C" void kernel_launch(void* const* d_in, const int* in_sizes, int n_in,
                              void* d_out, int out_size)
{
    (void)in_sizes; (void)n_in; (void)out_size;

    const float* x_gene    = (const float*)d_in[0];
    const float* x_disease = (const float*)d_in[1];
    const int*   ei_g2d    = (const int*)d_in[2];
    const int*   ei_d2g    = (const int*)d_in[3];
    const int*   eli       = (const int*)d_in[6];
    const float* Wn_g      = (const float*)d_in[7];
    const float* bn_g      = (const float*)d_in[8];
    const float* Wn_d      = (const float*)d_in[9];
    const float* bn_d      = (const float*)d_in[10];
    const float* W1        = (const float*)d_in[17];
    const float* b1        = (const float*)d_in[18];
    const float* W2        = (const float*)d_in[19];
    const float* b2        = (const float*)d_in[20];

    float* out   = (float*)d_out;
    float* pred  = out;
    float* z_gen = out + NEL;
    float* z_dis = out + NEL + (size_t)NGN * CC;

    cudaFuncSetAttribute(fused_gemm_kernel,
                         cudaFuncAttributeMaxDynamicSharedMemorySize, SMEM_TOTAL);

    // 1) isolation masks
    init_masks_kernel<<<(NGN + 255) / 256, 256>>>();
    scatter_masks_kernel<<<(NE + 255) / 256, 256>>>(ei_g2d + NE, ei_d2g + NE);

    // 2) weight split images (4 x 32KB hi + 32KB lo, swizzled W^T)
    wsplit_kernel<<<4, 256>>>(Wn_g, Wn_d, W1);

    // 3) fused (z, u) for both node types in one grid
    fused_gemm_kernel<<<2 * TILES, 512, SMEM_TOTAL>>>(
        x_gene, x_disease, bn_g, bn_d, b1, z_gen, z_dis);

    // 4) edge scores
    pred_kernel<<<(NEL * 32 + 255) / 256, 256>>>(eli, eli + NEL, W2, b2, pred);
}

// round 12
// speedup vs baseline: 1.7503x; 1.1195x over previous
#include <cuda_runtime.h>
#include <cuda_bf16.h>
#include <cstdint>
#include <cstddef>

#define NGN 100000
#define NDN 100000
#define NE  400000
#define NEL 200000
#define CC  128
#define TM  128
#define TILES ((NGN + TM - 1) / TM)      // 782
#define NPER  74                         // persistent blocks per side
#define CHUNK_ELEMS 8192                 // 128 rows * 64 bf16 = 16KB
#define TILE_IMG_ELEMS (2 * CHUNK_ELEMS) // 32KB image (2 chunks)

// smem layout (bytes): A-hi, A-lo (reused for Z-hi/Z-lo), W1 hi/lo, W2 hi/lo
#define SM_AH   0
#define SM_AL   32768
#define SM_W1H  65536
#define SM_W1L  98304
#define SM_W2H  131072
#define SM_W2L  163840
#define SMEM_TOTAL 196608

// ---------------------------------------------------------------------------
__device__ __align__(16) __nv_bfloat16 g_wimg[4][2][TILE_IMG_ELEMS]; // [mat][hi/lo]
__device__ __align__(16) float g_ug[(size_t)NGN * CC];
__device__ __align__(16) float g_ud[(size_t)NDN * CC];
__device__ unsigned char g_mask_g[NGN];
__device__ unsigned char g_mask_d[NDN];

// ---------------------------------------------------------------------------
__device__ __forceinline__ uint32_t smem_u32(const void* p) {
    uint32_t a;
    asm("{ .reg .u64 t; cvta.to.shared.u64 t, %1; cvt.u32.u64 %0, t; }"
        : "=r"(a) : "l"(p));
    return a;
}
__device__ __forceinline__ uint32_t swz(uint32_t off) {   // SW128 swizzle
    return off ^ ((off >> 3) & 0x70);
}
__device__ __forceinline__ void prefetch_l2(const void* p) {
    asm volatile("prefetch.global.L2 [%0];" :: "l"(p));
}

#define LDSM_X4(r0, r1, r2, r3, addr) \
    asm volatile("ldmatrix.sync.aligned.m8n8.x4.shared.b16 {%0,%1,%2,%3}, [%4];" \
        : "=r"(r0), "=r"(r1), "=r"(r2), "=r"(r3) : "r"(addr))

#define MMA16816(c, a, b) \
    asm volatile("mma.sync.aligned.m16n8k16.row.col.f32.bf16.bf16.f32 " \
        "{%0,%1,%2,%3}, {%4,%5,%6,%7}, {%8,%9}, {%0,%1,%2,%3};" \
        : "+f"((c)[0]), "+f"((c)[1]), "+f"((c)[2]), "+f"((c)[3]) \
        : "r"((a)[0]), "r"((a)[1]), "r"((a)[2]), "r"((a)[3]), \
          "r"((b)[0]), "r"((b)[1]))

// split fp32 -> bf16 hi + bf16 lo (residual)
__device__ __forceinline__ void split4(const float4 v, uint2& hv, uint2& lv) {
    __nv_bfloat16 h0 = __float2bfloat16(v.x), h1 = __float2bfloat16(v.y);
    __nv_bfloat16 h2 = __float2bfloat16(v.z), h3 = __float2bfloat16(v.w);
    float l0 = v.x - __bfloat162float(h0), l1 = v.y - __bfloat162float(h1);
    float l2 = v.z - __bfloat162float(h2), l3 = v.w - __bfloat162float(h3);
    __nv_bfloat162 hp0(h0, h1), hp1(h2, h3);
    __nv_bfloat162 lp0(__float2bfloat16(l0), __float2bfloat16(l1));
    __nv_bfloat162 lp1(__float2bfloat16(l2), __float2bfloat16(l3));
    hv.x = *(uint32_t*)&hp0; hv.y = *(uint32_t*)&hp1;
    lv.x = *(uint32_t*)&lp0; lv.y = *(uint32_t*)&lp1;
}
__device__ __forceinline__ void split2(float v0, float v1, uint32_t& h, uint32_t& l) {
    __nv_bfloat16 h0 = __float2bfloat16(v0), h1 = __float2bfloat16(v1);
    float l0 = v0 - __bfloat162float(h0), l1 = v1 - __bfloat162float(h1);
    __nv_bfloat162 hp(h0, h1);
    __nv_bfloat162 lp(__float2bfloat16(l0), __float2bfloat16(l1));
    h = *(uint32_t*)&hp; l = *(uint32_t*)&lp;
}

// ---------------------------------------------------------------------------
__global__ void init_masks_kernel() {
    int i = blockIdx.x * blockDim.x + threadIdx.x;
    if (i < NGN) g_mask_g[i] = 0;
    if (i < NDN) g_mask_d[i] = 0;
}
__global__ void scatter_masks_kernel(const int* __restrict__ dst_g2d,
                                     const int* __restrict__ dst_d2g) {
    int e = blockIdx.x * blockDim.x + threadIdx.x;
    if (e < NE) {
        g_mask_d[dst_g2d[e]] = 1;
        g_mask_g[dst_d2g[e]] = 1;
    }
}

// ---------------------------------------------------------------------------
// W split: W[128,128] (K x N) -> W^T image [n][k] bf16 hi/lo, SW128-swizzled.
// block b: 0=Wn_g 1=Wn_d 2=W1[:128] 3=W1[128:]
// ---------------------------------------------------------------------------
__global__ __launch_bounds__(256) void wsplit_kernel(
    const float* __restrict__ Wg, const float* __restrict__ Wd,
    const float* __restrict__ W1)
{
    const float* W = (blockIdx.x == 0) ? Wg : (blockIdx.x == 1) ? Wd
                   : (blockIdx.x == 2) ? W1 : (W1 + CC * CC);
    int n = threadIdx.x >> 1;
    int c = threadIdx.x & 1;
    char* ph = (char*)&g_wimg[blockIdx.x][0][(size_t)c * CHUNK_ELEMS];
    char* pl = (char*)&g_wimg[blockIdx.x][1][(size_t)c * CHUNK_ELEMS];
    #pragma unroll
    for (int kk = 0; kk < 64; kk += 4) {
        int k = c * 64 + kk;
        float4 v = make_float4(W[(size_t)(k + 0) * CC + n], W[(size_t)(k + 1) * CC + n],
                               W[(size_t)(k + 2) * CC + n], W[(size_t)(k + 3) * CC + n]);
        uint2 hv, lv;
        split4(v, hv, lv);
        uint32_t off = swz((uint32_t)(n * 128 + kk * 2));
        *(uint2*)(ph + off) = hv;
        *(uint2*)(pl + off) = lv;
    }
}

// ---------------------------------------------------------------------------
// Fused 3-product split-bf16 MMA (Ah*Wh + Ah*Wl + Al*Wh in one k-loop).
// Warp tile 32x32: wm in 0..3, wn in 0..3. Per kt: 8 LDSM.x4 -> 24 MMAs.
// ---------------------------------------------------------------------------
__device__ __forceinline__ void mma_stage(
    uint32_t abh, uint32_t abl, uint32_t bbh, uint32_t bbl,
    int wm, int wn, int lane, float acc[2][4][4])
{
    const int g = lane >> 3;
    const int r7 = lane & 7;
    const int arow = ((g & 1) << 3) + r7;
    const int akseg = (g >> 1) << 4;
    const int brow = ((g >> 1) << 3) + r7;
    const int bkseg = (g & 1) << 4;

    #pragma unroll
    for (int kt = 0; kt < 8; ++kt) {
        const uint32_t coff = (uint32_t)(kt >> 2) * 16384u;
        const int kb = (kt & 3) * 32;

        uint32_t ah[2][4], al[2][4];
        #pragma unroll
        for (int mt = 0; mt < 2; ++mt) {
            int row = wm * 32 + mt * 16 + arow;
            uint32_t so = coff + swz((uint32_t)(row * 128 + kb + akseg));
            LDSM_X4(ah[mt][0], ah[mt][1], ah[mt][2], ah[mt][3], abh + so);
            LDSM_X4(al[mt][0], al[mt][1], al[mt][2], al[mt][3], abl + so);
        }
        uint32_t wh[4][2], wl[4][2];
        #pragma unroll
        for (int h = 0; h < 2; ++h) {
            int n = wn * 32 + h * 16 + brow;
            uint32_t so = coff + swz((uint32_t)(n * 128 + kb + bkseg));
            uint32_t r0, r1, r2, r3;
            LDSM_X4(r0, r1, r2, r3, bbh + so);
            wh[h * 2][0] = r0;     wh[h * 2][1] = r1;
            wh[h * 2 + 1][0] = r2; wh[h * 2 + 1][1] = r3;
            LDSM_X4(r0, r1, r2, r3, bbl + so);
            wl[h * 2][0] = r0;     wl[h * 2][1] = r1;
            wl[h * 2 + 1][0] = r2; wl[h * 2 + 1][1] = r3;
        }
        #pragma unroll
        for (int p = 0; p < 3; ++p)
            #pragma unroll
            for (int mt = 0; mt < 2; ++mt)
                #pragma unroll
                for (int nt = 0; nt < 4; ++nt)
                    MMA16816(acc[mt][nt],
                             (p == 2) ? al[mt] : ah[mt],
                             (p == 1) ? wl[nt] : wh[nt]);
    }
}

// ---------------------------------------------------------------------------
// PERSISTENT fused kernel: 148 blocks (one per SM, single wave), 512 threads.
// Block b: side = b&1, lane-in-side = b>>1 (74 per side); loops tiles strided.
// W images loaded into smem ONCE; per tile: stage X, MMA1, epi1(z + re-split),
// MMA2, epi2(u). Next tile's X lines prefetched to L2 during compute.
// ---------------------------------------------------------------------------
__global__ __launch_bounds__(512, 1) void fused_gemm_kernel(
    const float* __restrict__ Xg, const float* __restrict__ Xd,
    const float* __restrict__ bn_g, const float* __restrict__ bn_d,
    const float* __restrict__ b1,
    float* __restrict__ z_gen, float* __restrict__ z_dis)
{
    extern __shared__ char smem[];
    const uint32_t sb = smem_u32(smem);
    const int tid = threadIdx.x;
    const int lane = tid & 31;
    const int wid = tid >> 5;
    const int wm = wid >> 2;   // 4 m-quarters (32 rows)
    const int wn = wid & 3;    // 4 n-quarters (32 cols)

    const bool sideB = (blockIdx.x & 1);
    const int idx = blockIdx.x >> 1;     // 0..73
    const float* X = sideB ? Xd : Xg;
    const float* bias1 = sideB ? bn_d : bn_g;
    const float* bias2 = sideB ? b1 : nullptr;
    const unsigned char* mask = sideB ? g_mask_d : g_mask_g;
    float* zout = sideB ? z_dis : z_gen;
    float* uout = sideB ? g_ud : g_ug;
    const int M = sideB ? NDN : NGN;

    // ---- load W images once ----
    {
        const uint4* s[4] = {(const uint4*)g_wimg[sideB ? 1 : 0][0],
                             (const uint4*)g_wimg[sideB ? 1 : 0][1],
                             (const uint4*)g_wimg[sideB ? 3 : 2][0],
                             (const uint4*)g_wimg[sideB ? 3 : 2][1]};
        uint4* d[4] = {(uint4*)(smem + SM_W1H), (uint4*)(smem + SM_W1L),
                       (uint4*)(smem + SM_W2H), (uint4*)(smem + SM_W2L)};
        #pragma unroll
        for (int bimg = 0; bimg < 4; ++bimg)
            #pragma unroll
            for (int i = 0; i < 4; ++i)
                d[bimg][i * 512 + tid] = s[bimg][i * 512 + tid];
        // prefetch first tile's X into L2
        prefetch_l2((const char*)(X + (size_t)idx * TM * CC) + tid * 128);
    }

    for (int t = idx; t < TILES; t += NPER) {
        const int rows_left = M - t * TM;

        // ---- stage X(t) -> bf16 hi/lo swizzled images ----
        {
            const float4* xs = (const float4*)(X + (size_t)t * TM * CC);
            #pragma unroll
            for (int i = 0; i < 8; ++i) {
                int q = i * 512 + tid;
                int row = q >> 5;
                int kk = (q & 31) << 2;
                float4 v = (row < rows_left) ? xs[q] : make_float4(0.f, 0.f, 0.f, 0.f);
                uint2 hv, lv;
                split4(v, hv, lv);
                uint32_t off = (uint32_t)((kk >> 6) * 16384)
                             + swz((uint32_t)(row * 128 + (kk & 63) * 2));
                *(uint2*)(smem + SM_AH + off) = hv;
                *(uint2*)(smem + SM_AL + off) = lv;
            }
            // prefetch next tile's X lines to L2 (hidden under MMA phases)
            if (t + NPER < TILES)
                prefetch_l2((const char*)(X + (size_t)(t + NPER) * TM * CC) + tid * 128);
        }
        __syncthreads();

        float acc[2][4][4];
        #pragma unroll
        for (int mt = 0; mt < 2; ++mt)
            #pragma unroll
            for (int nt = 0; nt < 4; ++nt)
                #pragma unroll
                for (int j = 0; j < 4; ++j) acc[mt][nt][j] = 0.0f;

        // ---- stage 1: z = x @ Wa ----
        mma_stage(sb + SM_AH, sb + SM_AL, sb + SM_W1H, sb + SM_W1L, wm, wn, lane, acc);
        __syncthreads();   // all warps done reading A images before overwrite

        // ---- epilogue 1: bias + relu*mask, write z, re-split into A buffers ----
        const int row_base = t * TM;
        #pragma unroll
        for (int mt = 0; mt < 2; ++mt) {
            const int rl0 = wm * 32 + mt * 16 + (lane >> 2);
            #pragma unroll
            for (int nt = 0; nt < 4; ++nt) {
                const int col = wn * 32 + nt * 8 + 2 * (lane & 3);
                const float2 bv = *(const float2*)&bias1[col];
                #pragma unroll
                for (int hh = 0; hh < 2; ++hh) {
                    const int rl = rl0 + hh * 8;
                    const int r = row_base + rl;
                    float v0 = acc[mt][nt][hh * 2 + 0] + bv.x;
                    float v1 = acc[mt][nt][hh * 2 + 1] + bv.y;
                    if (r < M) {
                        const float mmv = (float)mask[r];
                        v0 = fmaxf(v0, 0.0f) * mmv;
                        v1 = fmaxf(v1, 0.0f) * mmv;
                        *(float2*)(zout + (size_t)r * CC + col) = make_float2(v0, v1);
                        uint32_t h, l;
                        split2(v0, v1, h, l);
                        uint32_t off = (uint32_t)((col >> 6) * 16384)
                                     + swz((uint32_t)(rl * 128 + (col & 63) * 2));
                        *(uint32_t*)(smem + SM_AH + off) = h;
                        *(uint32_t*)(smem + SM_AL + off) = l;
                    }
                }
            }
        }
        __syncthreads();

        // ---- stage 2: u = z @ Wb ----
        #pragma unroll
        for (int mt = 0; mt < 2; ++mt)
            #pragma unroll
            for (int nt = 0; nt < 4; ++nt)
                #pragma unroll
                for (int j = 0; j < 4; ++j) acc[mt][nt][j] = 0.0f;

        mma_stage(sb + SM_AH, sb + SM_AL, sb + SM_W2H, sb + SM_W2L, wm, wn, lane, acc);

        // ---- epilogue 2: (+bias2), write u ----
        #pragma unroll
        for (int mt = 0; mt < 2; ++mt) {
            const int rl0 = wm * 32 + mt * 16 + (lane >> 2);
            #pragma unroll
            for (int nt = 0; nt < 4; ++nt) {
                const int col = wn * 32 + nt * 8 + 2 * (lane & 3);
                float2 bv = bias2 ? *(const float2*)&bias2[col] : make_float2(0.f, 0.f);
                #pragma unroll
                for (int hh = 0; hh < 2; ++hh) {
                    const int r = row_base + rl0 + hh * 8;
                    if (r < M) {
                        float v0 = acc[mt][nt][hh * 2 + 0] + bv.x;
                        float v1 = acc[mt][nt][hh * 2 + 1] + bv.y;
                        *(float2*)(uout + (size_t)r * CC + col) = make_float2(v0, v1);
                    }
                }
            }
        }
        __syncthreads();   // before next staging overwrites A images
    }
}

// ---------------------------------------------------------------------------
// Link prediction head: one warp per labeled edge.
// ---------------------------------------------------------------------------
__global__ __launch_bounds__(256) void pred_kernel(
    const int* __restrict__ erow, const int* __restrict__ ecol,
    const float* __restrict__ W2, const float* __restrict__ b2,
    float* __restrict__ pred)
{
    int warp = (blockIdx.x * blockDim.x + threadIdx.x) >> 5;
    int lane = threadIdx.x & 31;
    if (warp >= NEL) return;

    int r = erow[warp];
    int c = ecol[warp];
    const float4 ug = *(const float4*)(g_ug + (size_t)r * CC + lane * 4);
    const float4 ud = *(const float4*)(g_ud + (size_t)c * CC + lane * 4);
    const float4 w2 = *(const float4*)(W2 + lane * 4);

    float s = fmaxf(ug.x + ud.x, 0.f) * w2.x
            + fmaxf(ug.y + ud.y, 0.f) * w2.y
            + fmaxf(ug.z + ud.z, 0.f) * w2.z
            + fmaxf(ug.w + ud.w, 0.f) * w2.w;

    #pragma unroll
    for (int o = 16; o > 0; o >>= 1)
        s += __shfl_xor_sync(0xFFFFFFFFu, s, o);

    if (lane == 0) pred[warp] = s + b2[0];
}

// ---------------------------------------------------------------------------
extern "C" void kernel_launch(void* const* d_in, const int* in_sizes, int n_in,
                              void* d_out, int out_size)
{
    (void)in_sizes; (void)n_in; (void)out_size;

    const float* x_gene    = (const float*)d_in[0];
    const float* x_disease = (const float*)d_in[1];
    const int*   ei_g2d    = (const int*)d_in[2];
    const int*   ei_d2g    = (const int*)d_in[3];
    const int*   eli       = (const int*)d_in[6];
    const float* Wn_g      = (const float*)d_in[7];
    const float* bn_g      = (const float*)d_in[8];
    const float* Wn_d      = (const float*)d_in[9];
    const float* bn_d      = (const float*)d_in[10];
    const float* W1        = (const float*)d_in[17];
    const float* b1        = (const float*)d_in[18];
    const float* W2        = (const float*)d_in[19];
    const float* b2        = (const float*)d_in[20];

    float* out   = (float*)d_out;
    float* pred  = out;
    float* z_gen = out + NEL;
    float* z_dis = out + NEL + (size_t)NGN * CC;

    cudaFuncSetAttribute(fused_gemm_kernel,
                         cudaFuncAttributeMaxDynamicSharedMemorySize, SMEM_TOTAL);

    // 1) isolation masks
    init_masks_kernel<<<(NGN + 255) / 256, 256>>>();
    scatter_masks_kernel<<<(NE + 255) / 256, 256>>>(ei_g2d + NE, ei_d2g + NE);

    // 2) weight split images (4 x 32KB hi + 32KB lo, swizzled W^T)
    wsplit_kernel<<<4, 256>>>(Wn_g, Wn_d, W1);

    // 3) persistent fused (z, u) for both node types: 148 blocks, single wave
    fused_gemm_kernel<<<2 * NPER, 512, SMEM_TOTAL>>>(
        x_gene, x_disease, bn_g, bn_d, b1, z_gen, z_dis);

    // 4) edge scores
    pred_kernel<<<(NEL * 32 + 255) / 256, 256>>>(eli, eli + NEL, W2, b2, pred);
}